// round 14
// baseline (speedup 1.0000x reference)
#include <cuda_runtime.h>
#include <math.h>
#include <stdint.h>

#define NB 16
#define NC 128
#define NL 256
#define ND 512
#define ROWS (NB*NC)   // 2048

// ---------------- scratch (no allocations allowed) ----------------
__device__ float g_E0[ROWS*ND];
__device__ float g_E0tf[ROWS*ND];
__device__ float g_total[ROWS];
__device__ float g_QKV[ROWS*3*ND];
__device__ float g_ctx[ROWS*ND];
__device__ float g_Sp[4*NB*NC*NC];     // QK partial dots (4 split-K quarters)
__device__ float g_Jp[NB*NC*NC];       // full mask-joint dots
__device__ float g_P[2*ROWS*ND];
__device__ float g_E1[ROWS*ND];
__device__ float g_E1tf[ROWS*ND];
__device__ float g_H[ROWS*2*ND];
__device__ float g_Wqkv[ND*3*ND];
__device__ float g_Wo[ND*ND];
__device__ float g_W1[ND*2*ND];
__device__ float g_W2[2*ND*ND];

__device__ __forceinline__ uint32_t f2tf(float f) {
    uint32_t u;
    asm("cvt.rna.tf32.f32 %0, %1;" : "=r"(u) : "f"(f));
    return u;
}
__device__ __forceinline__ float f2tf_f(float f) { return __uint_as_float(f2tf(f)); }

// ---------------- fused weight converter ----------------
#define NW_QKV (ND*3*ND/4)
#define NW_O   (ND*ND/4)
#define NW_1   (ND*2*ND/4)
#define NW_2   (2*ND*ND/4)
__global__ void cvt_all_kernel(const float* __restrict__ wqkv, const float* __restrict__ wo,
                               const float* __restrict__ w1, const float* __restrict__ w2) {
    int i = blockIdx.x * blockDim.x + threadIdx.x;
    const float4* src; float4* dst; int off;
    if (i < NW_QKV)                 { src = (const float4*)wqkv; dst = (float4*)g_Wqkv; off = i; }
    else if (i < NW_QKV+NW_O)       { src = (const float4*)wo;   dst = (float4*)g_Wo;   off = i - NW_QKV; }
    else if (i < NW_QKV+NW_O+NW_1)  { src = (const float4*)w1;   dst = (float4*)g_W1;   off = i - NW_QKV - NW_O; }
    else                            { src = (const float4*)w2;   dst = (float4*)g_W2;   off = i - NW_QKV - NW_O - NW_1; }
    float4 v = src[off];
    v.x = f2tf_f(v.x); v.y = f2tf_f(v.y); v.z = f2tf_f(v.z); v.w = f2tf_f(v.w);
    dst[off] = v;
}

// ---------------- masked mean pool ----------------
__global__ void pool_kernel(const float* __restrict__ x,
                            const float* __restrict__ mask) {
    const int row = blockIdx.x;
    const int tid = threadIdx.x;          // 128 threads
    __shared__ float msh[NL];
    __shared__ float red[128];

    float m0 = mask[(size_t)row*NL + tid];
    float m1 = mask[(size_t)row*NL + 128 + tid];
    msh[tid] = m0; msh[tid + 128] = m1;
    red[tid] = m0 + m1;
    __syncthreads();
    #pragma unroll
    for (int s = 64; s > 0; s >>= 1) {
        if (tid < s) red[tid] += red[tid + s];
        __syncthreads();
    }
    const float msum = red[0];

    const float4* xr = reinterpret_cast<const float4*>(x) + (size_t)row*NL*(ND/4);
    float4 acc = make_float4(0.f,0.f,0.f,0.f);
    #pragma unroll 8
    for (int l = 0; l < NL; l++) {
        float4 v = __ldcs(&xr[(size_t)l*(ND/4) + tid]);
        float m = msh[l];
        acc.x += v.x*m; acc.y += v.y*m; acc.z += v.z*m; acc.w += v.w*m;
    }
    const float inv = 1.0f / fmaxf(msum, 1.0f);
    acc.x *= inv; acc.y *= inv; acc.z *= inv; acc.w *= inv;
    reinterpret_cast<float4*>(g_E0)[(size_t)row*(ND/4) + tid] = acc;
    float4 t;
    t.x = f2tf_f(acc.x); t.y = f2tf_f(acc.y); t.z = f2tf_f(acc.z); t.w = f2tf_f(acc.w);
    reinterpret_cast<float4*>(g_E0tf)[(size_t)row*(ND/4) + tid] = t;
    if (tid == 0) g_total[row] = msum;
}

// ---------------- TF32 tensor-core GEMM core ---------------------------------
#define EPI_BIAS 0
#define EPI_GELU 2

__device__ __forceinline__ float gelu_exact(float v) {
    return 0.5f * v * (1.0f + erff(v * 0.70710678118654752f));
}

__device__ __forceinline__ void mma_tf32(float* c, const uint32_t* a, const uint32_t* b) {
    asm volatile(
        "mma.sync.aligned.m16n8k8.row.col.f32.tf32.tf32.f32 "
        "{%0,%1,%2,%3}, {%4,%5,%6,%7}, {%8,%9}, {%0,%1,%2,%3};\n"
        : "+f"(c[0]), "+f"(c[1]), "+f"(c[2]), "+f"(c[3])
        : "r"(a[0]), "r"(a[1]), "r"(a[2]), "r"(a[3]),
          "r"(b[0]), "r"(b[1]));
}

__device__ __forceinline__ void cp_async16(uint32_t saddr, const void* g) {
    asm volatile("cp.async.cg.shared.global [%0], [%1], 16;\n" :: "r"(saddr), "l"(g));
}
#define CP_COMMIT() asm volatile("cp.async.commit_group;\n" ::: "memory")
#define CP_WAIT0()  asm volatile("cp.async.wait_group 0;\n" ::: "memory")

#define AS_STRIDE 36
#define BS_STRIDE 136

// ---- 256-thread GEMM: BM=64, BN=128, BK=32; 8 warps 2(m)x4(n).
template<int EPI>
__global__ __launch_bounds__(256)
void gemm_tc(const float* __restrict__ A, const float* __restrict__ B,
             const float* __restrict__ bias,
             float* __restrict__ C, int M, int N, int K) {
    __shared__ float As[2][64][AS_STRIDE];
    __shared__ float Bs[2][32][BS_STRIDE];

    const int tid  = threadIdx.x;
    const int warp = tid >> 5, lane = tid & 31;
    const int gq = lane >> 2, tq = lane & 3;
    const int wm = (warp & 1) * 32;
    const int wn = (warp >> 1) * 32;
    const int bm0 = blockIdx.y * 64;
    const int bn0 = blockIdx.x * 128;

    const float* Ag = A + (size_t)bm0 * K;
    const float* Bg = B + bn0;

    int arow[2], acol[2], brow[4], bcol[4];
    #pragma unroll
    for (int i = 0; i < 2; i++) {
        int c = tid + i * 256;
        arow[i] = c >> 3;  acol[i] = (c & 7) << 2;
    }
    #pragma unroll
    for (int i = 0; i < 4; i++) {
        int c = tid + i * 256;
        brow[i] = c >> 5;  bcol[i] = (c & 31) << 2;
    }

    auto load_stage = [&](int s, int kt) {
        const float* Agk = Ag + kt * 32;
        const float* Bgk = Bg + (size_t)kt * 32 * N;
        #pragma unroll
        for (int i = 0; i < 2; i++) {
            uint32_t sa = (uint32_t)__cvta_generic_to_shared(&As[s][arow[i]][acol[i]]);
            cp_async16(sa, Agk + (size_t)arow[i] * K + acol[i]);
        }
        #pragma unroll
        for (int i = 0; i < 4; i++) {
            uint32_t sb = (uint32_t)__cvta_generic_to_shared(&Bs[s][brow[i]][bcol[i]]);
            cp_async16(sb, Bgk + (size_t)brow[i] * N + bcol[i]);
        }
    };

    float c[2][4][4];
    #pragma unroll
    for (int i = 0; i < 2; i++)
        #pragma unroll
        for (int j = 0; j < 4; j++)
            #pragma unroll
            for (int k = 0; k < 4; k++) c[i][j][k] = 0.f;

    const int ntk = K >> 5;
    load_stage(0, 0); CP_COMMIT();

    for (int kt = 0; kt < ntk; kt++) {
        CP_WAIT0();
        __syncthreads();
        if (kt + 1 < ntk) { load_stage((kt + 1) & 1, kt + 1); CP_COMMIT(); }
        const int s = kt & 1;
        #pragma unroll
        for (int k0 = 0; k0 < 32; k0 += 8) {
            uint32_t af[2][4], bf[4][2];
            #pragma unroll
            for (int mt = 0; mt < 2; mt++) {
                const int r0 = wm + mt * 16 + gq;
                af[mt][0] = __float_as_uint(As[s][r0][k0 + tq]);
                af[mt][1] = __float_as_uint(As[s][r0 + 8][k0 + tq]);
                af[mt][2] = __float_as_uint(As[s][r0][k0 + tq + 4]);
                af[mt][3] = __float_as_uint(As[s][r0 + 8][k0 + tq + 4]);
            }
            #pragma unroll
            for (int nt = 0; nt < 4; nt++) {
                bf[nt][0] = __float_as_uint(Bs[s][k0 + tq][wn + nt * 8 + gq]);
                bf[nt][1] = __float_as_uint(Bs[s][k0 + tq + 4][wn + nt * 8 + gq]);
            }
            #pragma unroll
            for (int mt = 0; mt < 2; mt++)
                #pragma unroll
                for (int nt = 0; nt < 4; nt++)
                    mma_tf32(c[mt][nt], af[mt], bf[nt]);
        }
        __syncthreads();
    }

    #pragma unroll
    for (int mt = 0; mt < 2; mt++) {
        #pragma unroll
        for (int half = 0; half < 2; half++) {
            const int row = bm0 + wm + mt * 16 + gq + half * 8;
            #pragma unroll
            for (int nt = 0; nt < 4; nt++) {
                const int col = bn0 + wn + nt * 8 + 2 * tq;
                float2 r;
                r.x = c[mt][nt][half * 2 + 0];
                r.y = c[mt][nt][half * 2 + 1];
                float2 bv = *reinterpret_cast<const float2*>(bias + col);
                r.x += bv.x; r.y += bv.y;
                if (EPI == EPI_GELU) {
                    r.x = f2tf_f(gelu_exact(r.x));
                    r.y = f2tf_f(gelu_exact(r.y));
                }
                *reinterpret_cast<float2*>(C + (size_t)row * N + col) = r;
            }
        }
    }
}

// Split-K=2, 256-thread variant: writes raw partial (no bias).
__global__ __launch_bounds__(256)
void gemm_tc_sk(const float* __restrict__ A, const float* __restrict__ B,
                float* __restrict__ Cpart, int M, int N, int K) {
    __shared__ float As[2][64][AS_STRIDE];
    __shared__ float Bs[2][32][BS_STRIDE];

    const int tid  = threadIdx.x;
    const int warp = tid >> 5, lane = tid & 31;
    const int gq = lane >> 2, tq = lane & 3;
    const int wm = (warp & 1) * 32;
    const int wn = (warp >> 1) * 32;
    const int bm0 = blockIdx.y * 64;
    const int bn0 = blockIdx.x * 128;
    const int kz  = blockIdx.z;
    const int Kh  = K >> 1;

    const float* Ag = A + (size_t)bm0 * K + (size_t)kz * Kh;
    const float* Bg = B + bn0 + (size_t)kz * Kh * N;
    float* Cp = Cpart + (size_t)kz * M * N;

    int arow[2], acol[2], brow[4], bcol[4];
    #pragma unroll
    for (int i = 0; i < 2; i++) {
        int c = tid + i * 256;
        arow[i] = c >> 3;  acol[i] = (c & 7) << 2;
    }
    #pragma unroll
    for (int i = 0; i < 4; i++) {
        int c = tid + i * 256;
        brow[i] = c >> 5;  bcol[i] = (c & 31) << 2;
    }

    auto load_stage = [&](int s, int kt) {
        const float* Agk = Ag + kt * 32;
        const float* Bgk = Bg + (size_t)kt * 32 * N;
        #pragma unroll
        for (int i = 0; i < 2; i++) {
            uint32_t sa = (uint32_t)__cvta_generic_to_shared(&As[s][arow[i]][acol[i]]);
            cp_async16(sa, Agk + (size_t)arow[i] * K + acol[i]);
        }
        #pragma unroll
        for (int i = 0; i < 4; i++) {
            uint32_t sb = (uint32_t)__cvta_generic_to_shared(&Bs[s][brow[i]][bcol[i]]);
            cp_async16(sb, Bgk + (size_t)brow[i] * N + bcol[i]);
        }
    };

    float c[2][4][4];
    #pragma unroll
    for (int i = 0; i < 2; i++)
        #pragma unroll
        for (int j = 0; j < 4; j++)
            #pragma unroll
            for (int k = 0; k < 4; k++) c[i][j][k] = 0.f;

    const int ntk = Kh >> 5;
    load_stage(0, 0); CP_COMMIT();

    for (int kt = 0; kt < ntk; kt++) {
        CP_WAIT0();
        __syncthreads();
        if (kt + 1 < ntk) { load_stage((kt + 1) & 1, kt + 1); CP_COMMIT(); }
        const int s = kt & 1;
        #pragma unroll
        for (int k0 = 0; k0 < 32; k0 += 8) {
            uint32_t af[2][4], bf[4][2];
            #pragma unroll
            for (int mt = 0; mt < 2; mt++) {
                const int r0 = wm + mt * 16 + gq;
                af[mt][0] = __float_as_uint(As[s][r0][k0 + tq]);
                af[mt][1] = __float_as_uint(As[s][r0 + 8][k0 + tq]);
                af[mt][2] = __float_as_uint(As[s][r0][k0 + tq + 4]);
                af[mt][3] = __float_as_uint(As[s][r0 + 8][k0 + tq + 4]);
            }
            #pragma unroll
            for (int nt = 0; nt < 4; nt++) {
                bf[nt][0] = __float_as_uint(Bs[s][k0 + tq][wn + nt * 8 + gq]);
                bf[nt][1] = __float_as_uint(Bs[s][k0 + tq + 4][wn + nt * 8 + gq]);
            }
            #pragma unroll
            for (int mt = 0; mt < 2; mt++)
                #pragma unroll
                for (int nt = 0; nt < 4; nt++)
                    mma_tf32(c[mt][nt], af[mt], bf[nt]);
        }
        __syncthreads();
    }

    #pragma unroll
    for (int mt = 0; mt < 2; mt++)
        #pragma unroll
        for (int half = 0; half < 2; half++) {
            const int row = bm0 + wm + mt * 16 + gq + half * 8;
            #pragma unroll
            for (int nt = 0; nt < 4; nt++) {
                const int col = bn0 + wn + nt * 8 + 2 * tq;
                float2 r;
                r.x = c[mt][nt][half * 2 + 0];
                r.y = c[mt][nt][half * 2 + 1];
                *reinterpret_cast<float2*>(Cp + (size_t)row * N + col) = r;
            }
        }
}

// ------------- attention: QK partial dots (4 split-K quarters) --------------
// grid (2 ktile, 2 qtile, NB*4), 128 threads. 4 stages of 32 dims.
#define ZOFF ((size_t)NB*NC*NC)

__global__ __launch_bounds__(128)
void attn_qk_tc(const float* __restrict__ unused) {
    __shared__ float As[2][64][AS_STRIDE];
    __shared__ float Bs[2][64][AS_STRIDE];

    const int tid  = threadIdx.x;
    const int warp = tid >> 5, lane = tid & 31;
    const int gq = lane >> 2, tq = lane & 3;
    const int wm = (warp & 1) * 32;
    const int wn = (warp >> 1) * 32;
    const int k0g = blockIdx.x * 64;
    const int q0  = blockIdx.y * 64;
    const int b   = blockIdx.z >> 2;
    const int kz  = blockIdx.z & 3;

    const float* Qb = g_QKV + (size_t)(b*NC + q0)*3*ND + kz*128;
    const float* Kb = g_QKV + (size_t)(b*NC + k0g)*3*ND + ND + kz*128;

    int rrow[4], rcol[4];
    #pragma unroll
    for (int i = 0; i < 4; i++) {
        int c = tid + i * 128;
        rrow[i] = c >> 3;  rcol[i] = (c & 7) << 2;
    }

    auto load_stage = [&](int g) {
        const int s = g & 1;
        const int off = g * 32;
        #pragma unroll
        for (int i = 0; i < 4; i++) {
            uint32_t sa = (uint32_t)__cvta_generic_to_shared(&As[s][rrow[i]][rcol[i]]);
            cp_async16(sa, Qb + (size_t)rrow[i] * 3*ND + off + rcol[i]);
            uint32_t sb = (uint32_t)__cvta_generic_to_shared(&Bs[s][rrow[i]][rcol[i]]);
            cp_async16(sb, Kb + (size_t)rrow[i] * 3*ND + off + rcol[i]);
        }
    };

    float cS[2][4][4];
    #pragma unroll
    for (int i = 0; i < 2; i++)
        #pragma unroll
        for (int j = 0; j < 4; j++)
            #pragma unroll
            for (int k = 0; k < 4; k++) cS[i][j][k] = 0.f;

    load_stage(0); CP_COMMIT();

    #pragma unroll
    for (int g = 0; g < 4; g++) {
        CP_WAIT0();
        __syncthreads();
        if (g + 1 < 4) { load_stage(g + 1); CP_COMMIT(); }
        const int s = g & 1;
        #pragma unroll
        for (int k0 = 0; k0 < 32; k0 += 8) {
            uint32_t af[2][4], bf[4][2];
            #pragma unroll
            for (int mt = 0; mt < 2; mt++) {
                const int r0 = wm + mt * 16 + gq;
                af[mt][0] = __float_as_uint(As[s][r0][k0 + tq]);
                af[mt][1] = __float_as_uint(As[s][r0 + 8][k0 + tq]);
                af[mt][2] = __float_as_uint(As[s][r0][k0 + tq + 4]);
                af[mt][3] = __float_as_uint(As[s][r0 + 8][k0 + tq + 4]);
            }
            #pragma unroll
            for (int nt = 0; nt < 4; nt++) {
                bf[nt][0] = __float_as_uint(Bs[s][wn + nt * 8 + gq][k0 + tq]);
                bf[nt][1] = __float_as_uint(Bs[s][wn + nt * 8 + gq][k0 + tq + 4]);
            }
            #pragma unroll
            for (int mt = 0; mt < 2; mt++)
                #pragma unroll
                for (int nt = 0; nt < 4; nt++)
                    mma_tf32(cS[mt][nt], af[mt], bf[nt]);
        }
        __syncthreads();
    }

    #pragma unroll
    for (int mt = 0; mt < 2; mt++)
        #pragma unroll
        for (int half = 0; half < 2; half++) {
            const int row = q0 + wm + mt * 16 + gq + half * 8;
            #pragma unroll
            for (int nt = 0; nt < 4; nt++) {
                const int col = k0g + wn + nt * 8 + 2 * tq;
                const size_t idx = (size_t)kz*ZOFF + ((size_t)b*NC + row)*NC + col;
                float2 rs;
                rs.x = cS[mt][nt][half*2 + 0]; rs.y = cS[mt][nt][half*2 + 1];
                *reinterpret_cast<float2*>(g_Sp + idx) = rs;
            }
        }
}

// ------------- attention: mask-joint dots (mask only, runs under pool) ------
// grid (2 ktile, 2 qtile, NB), 128 threads. 8 stages over K=256.
__global__ __launch_bounds__(128)
void attn_joint_tc(const float* __restrict__ mask) {
    __shared__ float As[2][64][AS_STRIDE];
    __shared__ float Bs[2][64][AS_STRIDE];

    const int tid  = threadIdx.x;
    const int warp = tid >> 5, lane = tid & 31;
    const int gq = lane >> 2, tq = lane & 3;
    const int wm = (warp & 1) * 32;
    const int wn = (warp >> 1) * 32;
    const int k0g = blockIdx.x * 64;
    const int q0  = blockIdx.y * 64;
    const int b   = blockIdx.z;

    const float* Mq = mask + (size_t)(b*NC + q0)*NL;
    const float* Mk = mask + (size_t)(b*NC + k0g)*NL;

    int rrow[4], rcol[4];
    #pragma unroll
    for (int i = 0; i < 4; i++) {
        int c = tid + i * 128;
        rrow[i] = c >> 3;  rcol[i] = (c & 7) << 2;
    }

    auto load_stage = [&](int g) {
        const int s = g & 1;
        const int off = g * 32;
        #pragma unroll
        for (int i = 0; i < 4; i++) {
            uint32_t sa = (uint32_t)__cvta_generic_to_shared(&As[s][rrow[i]][rcol[i]]);
            cp_async16(sa, Mq + (size_t)rrow[i] * NL + off + rcol[i]);
            uint32_t sb = (uint32_t)__cvta_generic_to_shared(&Bs[s][rrow[i]][rcol[i]]);
            cp_async16(sb, Mk + (size_t)rrow[i] * NL + off + rcol[i]);
        }
    };

    float cJ[2][4][4];
    #pragma unroll
    for (int i = 0; i < 2; i++)
        #pragma unroll
        for (int j = 0; j < 4; j++)
            #pragma unroll
            for (int k = 0; k < 4; k++) cJ[i][j][k] = 0.f;

    load_stage(0); CP_COMMIT();

    #pragma unroll
    for (int g = 0; g < 8; g++) {
        CP_WAIT0();
        __syncthreads();
        if (g + 1 < 8) { load_stage(g + 1); CP_COMMIT(); }
        const int s = g & 1;
        #pragma unroll
        for (int k0 = 0; k0 < 32; k0 += 8) {
            uint32_t af[2][4], bf[4][2];
            #pragma unroll
            for (int mt = 0; mt < 2; mt++) {
                const int r0 = wm + mt * 16 + gq;
                af[mt][0] = __float_as_uint(As[s][r0][k0 + tq]);
                af[mt][1] = __float_as_uint(As[s][r0 + 8][k0 + tq]);
                af[mt][2] = __float_as_uint(As[s][r0][k0 + tq + 4]);
                af[mt][3] = __float_as_uint(As[s][r0 + 8][k0 + tq + 4]);
            }
            #pragma unroll
            for (int nt = 0; nt < 4; nt++) {
                bf[nt][0] = __float_as_uint(Bs[s][wn + nt * 8 + gq][k0 + tq]);
                bf[nt][1] = __float_as_uint(Bs[s][wn + nt * 8 + gq][k0 + tq + 4]);
            }
            #pragma unroll
            for (int mt = 0; mt < 2; mt++)
                #pragma unroll
                for (int nt = 0; nt < 4; nt++)
                    mma_tf32(cJ[mt][nt], af[mt], bf[nt]);
        }
        __syncthreads();
    }

    #pragma unroll
    for (int mt = 0; mt < 2; mt++)
        #pragma unroll
        for (int half = 0; half < 2; half++) {
            const int row = q0 + wm + mt * 16 + gq + half * 8;
            #pragma unroll
            for (int nt = 0; nt < 4; nt++) {
                const int col = k0g + wn + nt * 8 + 2 * tq;
                const size_t idx = ((size_t)b*NC + row)*NC + col;
                float2 rj;
                rj.x = cJ[mt][nt][half*2 + 0]; rj.y = cJ[mt][nt][half*2 + 1];
                *reinterpret_cast<float2*>(g_Jp + idx) = rj;
            }
        }
}

// ---------------- attention phase 2: modulate + softmax + AV ----------------
__global__ __launch_bounds__(128)
void attn_av(const float* __restrict__ unused) {
    __shared__ float S_sh[8*128];
    __shared__ float v_sh[16*260];

    const int b   = blockIdx.y;
    const int c0  = blockIdx.x * 8;
    const int z   = blockIdx.z;          // output dim half
    const int tid = threadIdx.x;
    const float scale = 0.04419417382415922f;

    {
        const int row = tid >> 4;
        const int sub = tid & 15;
        const size_t base = ((size_t)b*NC + c0 + row)*NC;
        const float tq = g_total[b*NC + c0 + row];
        float v[8];
        float mx = -1e30f;
        #pragma unroll
        for (int i = 0; i < 8; i++) {
            const int e = sub + 16*i;
            float a  = (g_Sp[base + e] + g_Sp[ZOFF + base + e])
                     + (g_Sp[2*ZOFF + base + e] + g_Sp[3*ZOFF + base + e]);
            float jj = g_Jp[base + e];
            float tk = g_total[b*NC + e];
            float ov = 2.0f * jj / fmaxf(tq + tk, 1.0f);
            v[i] = a * scale * (0.5f + 0.5f * ov);
            mx = fmaxf(mx, v[i]);
        }
        #pragma unroll
        for (int m = 1; m < 16; m <<= 1)
            mx = fmaxf(mx, __shfl_xor_sync(0xffffffffu, mx, m));
        float sm = 0.f;
        #pragma unroll
        for (int i = 0; i < 8; i++) { v[i] = expf(v[i] - mx); sm += v[i]; }
        #pragma unroll
        for (int m = 1; m < 16; m <<= 1)
            sm += __shfl_xor_sync(0xffffffffu, sm, m);
        const float inv = 1.0f / sm;
        #pragma unroll
        for (int i = 0; i < 8; i++)
            S_sh[row*128 + sub + 16*i] = v[i] * inv;
    }
    __syncthreads();

    float2 o[8];
    #pragma unroll
    for (int r = 0; r < 8; r++) o[r] = make_float2(0.f, 0.f);
    const int d0 = tid * 2;

    for (int ch = 0; ch < 8; ch++) {
        #pragma unroll
        for (int i = 0; i < 8; i++) {
            int c = tid + i * 128;
            int r = c >> 6, col = (c & 63) << 2;
            float4 v = *reinterpret_cast<const float4*>(
                g_QKV + (size_t)(b*NC + ch*16 + r)*3*ND + 2*ND + z*256 + col);
            *reinterpret_cast<float4*>(v_sh + r*260 + col) = v;
        }
        __syncthreads();
        #pragma unroll
        for (int ee = 0; ee < 16; ee++) {
            float2 v2 = *reinterpret_cast<const float2*>(v_sh + ee*260 + d0);
            const int eg = ch*16 + ee;
            #pragma unroll
            for (int r = 0; r < 8; r++) {
                float a = S_sh[r*128 + eg];
                o[r].x += a*v2.x; o[r].y += a*v2.y;
            }
        }
        __syncthreads();
    }

    #pragma unroll
    for (int r = 0; r < 8; r++) {
        float2 t;
        t.x = f2tf_f(o[r].x); t.y = f2tf_f(o[r].y);
        *reinterpret_cast<float2*>(g_ctx + (size_t)(b*NC + c0 + r)*ND + z*256 + d0) = t;
    }
}

// ------------- LayerNorm combine: v = P0 + P1 + bias + Res, then LN ---------
template<bool WRITE_TF>
__global__ __launch_bounds__(128)
void ln_comb_kernel(const float* __restrict__ P,
                    const float* __restrict__ Res,
                    const float* __restrict__ bias,
                    const float* __restrict__ g, const float* __restrict__ be,
                    float* __restrict__ out, float* __restrict__ out_tf) {
    const int row = blockIdx.x;
    const int tid = threadIdx.x;   // 128
    __shared__ float red_s[128];
    __shared__ float red_q[128];

    const size_t idx = (size_t)row*(ND/4) + tid;
    float4 p0 = reinterpret_cast<const float4*>(P)[idx];
    float4 p1 = reinterpret_cast<const float4*>(P + (size_t)ROWS*ND)[idx];
    float4 rs = reinterpret_cast<const float4*>(Res)[idx];
    float4 bb = reinterpret_cast<const float4*>(bias)[tid];
    float4 v;
    v.x = p0.x + p1.x + bb.x + rs.x;
    v.y = p0.y + p1.y + bb.y + rs.y;
    v.z = p0.z + p1.z + bb.z + rs.z;
    v.w = p0.w + p1.w + bb.w + rs.w;

    float s  = v.x + v.y + v.z + v.w;
    float sq = v.x*v.x + v.y*v.y + v.z*v.z + v.w*v.w;
    red_s[tid] = s; red_q[tid] = sq;
    __syncthreads();
    #pragma unroll
    for (int st = 64; st > 0; st >>= 1) {
        if (tid < st) { red_s[tid] += red_s[tid+st]; red_q[tid] += red_q[tid+st]; }
        __syncthreads();
    }
    const float mean = red_s[0] * (1.0f/ND);
    const float var  = red_q[0] * (1.0f/ND) - mean*mean;
    const float inv  = rsqrtf(var + 1e-5f);

    float4 g4 = reinterpret_cast<const float4*>(g)[tid];
    float4 b4 = reinterpret_cast<const float4*>(be)[tid];
    float4 r;
    r.x = (v.x - mean)*inv*g4.x + b4.x;
    r.y = (v.y - mean)*inv*g4.y + b4.y;
    r.z = (v.z - mean)*inv*g4.z + b4.z;
    r.w = (v.w - mean)*inv*g4.w + b4.w;
    reinterpret_cast<float4*>(out)[idx] = r;
    if (WRITE_TF) {
        float4 t;
        t.x = f2tf_f(r.x); t.y = f2tf_f(r.y); t.z = f2tf_f(r.z); t.w = f2tf_f(r.w);
        reinterpret_cast<float4*>(out_tf)[idx] = t;
    }
}

// ---------------- launch ----------------------------------------------------
extern "C" void kernel_launch(void* const* d_in, const int* in_sizes, int n_in,
                              void* d_out, int out_size) {
    const float* x    = (const float*)d_in[0];
    const float* mask = (const float*)d_in[1];
    const float* Wqkv = (const float*)d_in[2];
    const float* bqkv = (const float*)d_in[3];
    const float* Wo   = (const float*)d_in[4];
    const float* bo   = (const float*)d_in[5];
    const float* W1   = (const float*)d_in[6];
    const float* b1   = (const float*)d_in[7];
    const float* W2   = (const float*)d_in[8];
    const float* b2   = (const float*)d_in[9];
    const float* g1   = (const float*)d_in[10];
    const float* be1  = (const float*)d_in[11];
    const float* g2   = (const float*)d_in[12];
    const float* be2  = (const float*)d_in[13];
    float* out = (float*)d_out;

    float *E0, *E0tf, *QKV, *ctx, *P, *E1, *E1tf, *H;
    float *Wqkv_tf, *Wo_tf, *W1_tf, *W2_tf;
    cudaGetSymbolAddress((void**)&E0,   g_E0);
    cudaGetSymbolAddress((void**)&E0tf, g_E0tf);
    cudaGetSymbolAddress((void**)&QKV,  g_QKV);
    cudaGetSymbolAddress((void**)&ctx,  g_ctx);
    cudaGetSymbolAddress((void**)&P,    g_P);
    cudaGetSymbolAddress((void**)&E1,   g_E1);
    cudaGetSymbolAddress((void**)&E1tf, g_E1tf);
    cudaGetSymbolAddress((void**)&H,    g_H);
    cudaGetSymbolAddress((void**)&Wqkv_tf, g_Wqkv);
    cudaGetSymbolAddress((void**)&Wo_tf,   g_Wo);
    cudaGetSymbolAddress((void**)&W1_tf,   g_W1);
    cudaGetSymbolAddress((void**)&W2_tf,   g_W2);

    // Side stream: mask-only + weight-only work overlapped under the
    // memory-bound pool. Created per call; graph replays are free.
    cudaStream_t s1;
    cudaStreamCreateWithFlags(&s1, cudaStreamNonBlocking);
    cudaEvent_t evFork, evSide;
    cudaEventCreateWithFlags(&evFork, cudaEventDisableTiming);
    cudaEventCreateWithFlags(&evSide, cudaEventDisableTiming);

    cudaEventRecord(evFork, 0);
    cudaStreamWaitEvent(s1, evFork, 0);

    // s1 (compute-light, mask/weights only): cvt + mask-joint GEMM
    cvt_all_kernel<<<(NW_QKV+NW_O+NW_1+NW_2)/256, 256, 0, s1>>>(Wqkv, Wo, W1, W2);
    attn_joint_tc<<<dim3(2, 2, NB), 128, 0, s1>>>(mask);
    cudaEventRecord(evSide, s1);

    // s0: masked mean pool (HBM-bound, x + mask)
    pool_kernel<<<ROWS, 128>>>(x, mask);

    // join before QKV (needs converted weights)
    cudaStreamWaitEvent(0, evSide, 0);

    // QKV = E0 @ Wqkv + bqkv     (2048 x 1536 x 512)
    gemm_tc<EPI_BIAS><<<dim3(3*ND/128, ROWS/64), 256>>>(E0tf, Wqkv_tf, bqkv, QKV, ROWS, 3*ND, ND);

    // attention QK partial dots (4 split-K quarters)
    attn_qk_tc<<<dim3(2, 2, NB*4), 128>>>(mask);
    // modulate + softmax + AV (dim-half split), writes ctx tf32
    attn_av<<<dim3(NC/8, NB, 2), 128>>>(mask);

    // P = ctx @ Wo (split-K=2 partials)   (2048 x 512 x 512)
    gemm_tc_sk<<<dim3(ND/128, ROWS/64, 2), 256>>>(ctx, Wo_tf, P, ROWS, ND, ND);

    // E1 = LN(P0+P1+bo+E0)
    ln_comb_kernel<true><<<ROWS, 128>>>(P, E0, bo, g1, be1, E1, E1tf);

    // H = gelu(E1 @ W1 + b1)     (2048 x 1024 x 512)
    gemm_tc<EPI_GELU><<<dim3(2*ND/128, ROWS/64), 256>>>(E1tf, W1_tf, b1, H, ROWS, 2*ND, ND);

    // P = H @ W2 (split-K=2 partials)     (2048 x 512 x 1024)
    gemm_tc_sk<<<dim3(ND/128, ROWS/64, 2), 256>>>(H, W2_tf, P, ROWS, ND, 2*ND);

    // out = LN(P0+P1+b2+E1)
    ln_comb_kernel<false><<<ROWS, 128>>>(P, E1, b2, g2, be2, out, nullptr);

    cudaEventDestroy(evFork);
    cudaEventDestroy(evSide);
    cudaStreamDestroy(s1);
}

// round 15
// speedup vs baseline: 1.0066x; 1.0066x over previous
#include <cuda_runtime.h>
#include <math.h>
#include <stdint.h>

#define NB 16
#define NC 128
#define NL 256
#define ND 512
#define ROWS (NB*NC)   // 2048

// ---------------- scratch (no allocations allowed) ----------------
__device__ float g_E0[ROWS*ND];
__device__ float g_total[ROWS];
__device__ float g_QKV[ROWS*3*ND];
__device__ float g_ctx[ROWS*ND];
__device__ float g_Sp[4*NB*NC*NC];     // QK partial dots (4 split-K quarters)
__device__ float g_Jp[4*NB*NC*NC];     // mask-joint partial dots
__device__ float g_P[2*ROWS*ND];
__device__ float g_E1[ROWS*ND];
__device__ float g_H[ROWS*2*ND];
__device__ float g_Wqkv[ND*3*ND];
__device__ float g_Wo[ND*ND];
__device__ float g_W1[ND*2*ND];
__device__ float g_W2[2*ND*ND];

__device__ __forceinline__ uint32_t f2tf(float f) {
    uint32_t u;
    asm("cvt.rna.tf32.f32 %0, %1;" : "=r"(u) : "f"(f));
    return u;
}
__device__ __forceinline__ float f2tf_f(float f) { return __uint_as_float(f2tf(f)); }

// ---------------- fused weight converter ----------------
#define NW_QKV (ND*3*ND/4)
#define NW_O   (ND*ND/4)
#define NW_1   (ND*2*ND/4)
#define NW_2   (2*ND*ND/4)
__global__ void cvt_all_kernel(const float* __restrict__ wqkv, const float* __restrict__ wo,
                               const float* __restrict__ w1, const float* __restrict__ w2) {
    int i = blockIdx.x * blockDim.x + threadIdx.x;
    const float4* src; float4* dst; int off;
    if (i < NW_QKV)                 { src = (const float4*)wqkv; dst = (float4*)g_Wqkv; off = i; }
    else if (i < NW_QKV+NW_O)       { src = (const float4*)wo;   dst = (float4*)g_Wo;   off = i - NW_QKV; }
    else if (i < NW_QKV+NW_O+NW_1)  { src = (const float4*)w1;   dst = (float4*)g_W1;   off = i - NW_QKV - NW_O; }
    else                            { src = (const float4*)w2;   dst = (float4*)g_W2;   off = i - NW_QKV - NW_O - NW_1; }
    float4 v = src[off];
    v.x = f2tf_f(v.x); v.y = f2tf_f(v.y); v.z = f2tf_f(v.z); v.w = f2tf_f(v.w);
    dst[off] = v;
}

// ---------------- masked mean pool ----------------
__global__ void pool_kernel(const float* __restrict__ x,
                            const float* __restrict__ mask) {
    const int row = blockIdx.x;
    const int tid = threadIdx.x;          // 128 threads
    __shared__ float msh[NL];
    __shared__ float red[128];

    float m0 = mask[(size_t)row*NL + tid];
    float m1 = mask[(size_t)row*NL + 128 + tid];
    msh[tid] = m0; msh[tid + 128] = m1;
    red[tid] = m0 + m1;
    __syncthreads();
    #pragma unroll
    for (int s = 64; s > 0; s >>= 1) {
        if (tid < s) red[tid] += red[tid + s];
        __syncthreads();
    }
    const float msum = red[0];

    const float4* xr = reinterpret_cast<const float4*>(x) + (size_t)row*NL*(ND/4);
    float4 acc = make_float4(0.f,0.f,0.f,0.f);
    #pragma unroll 8
    for (int l = 0; l < NL; l++) {
        float4 v = __ldcs(&xr[(size_t)l*(ND/4) + tid]);
        float m = msh[l];
        acc.x += v.x*m; acc.y += v.y*m; acc.z += v.z*m; acc.w += v.w*m;
    }
    const float inv = 1.0f / fmaxf(msum, 1.0f);
    acc.x *= inv; acc.y *= inv; acc.z *= inv; acc.w *= inv;
    reinterpret_cast<float4*>(g_E0)[(size_t)row*(ND/4) + tid] = acc;
    if (tid == 0) g_total[row] = msum;
}

// ---------------- TF32 tensor-core GEMM core ---------------------------------
#define EPI_BIAS 0
#define EPI_GELU 2

__device__ __forceinline__ float gelu_exact(float v) {
    return 0.5f * v * (1.0f + erff(v * 0.70710678118654752f));
}

__device__ __forceinline__ void mma_tf32(float* c, const uint32_t* a, const uint32_t* b) {
    asm volatile(
        "mma.sync.aligned.m16n8k8.row.col.f32.tf32.tf32.f32 "
        "{%0,%1,%2,%3}, {%4,%5,%6,%7}, {%8,%9}, {%0,%1,%2,%3};\n"
        : "+f"(c[0]), "+f"(c[1]), "+f"(c[2]), "+f"(c[3])
        : "r"(a[0]), "r"(a[1]), "r"(a[2]), "r"(a[3]),
          "r"(b[0]), "r"(b[1]));
}

__device__ __forceinline__ void cp_async16(uint32_t saddr, const void* g) {
    asm volatile("cp.async.cg.shared.global [%0], [%1], 16;\n" :: "r"(saddr), "l"(g));
}
#define CP_COMMIT() asm volatile("cp.async.commit_group;\n" ::: "memory")
#define CP_WAIT0()  asm volatile("cp.async.wait_group 0;\n" ::: "memory")

#define AS_STRIDE 36
#define BS_STRIDE 136

// ---- 256-thread GEMM: BM=64, BN=128, BK=32; 8 warps 2(m)x4(n).
// A operand is raw fp32 (HW RZ-truncates to tf32); B is rna-preconverted.
template<int EPI>
__global__ __launch_bounds__(256)
void gemm_tc(const float* __restrict__ A, const float* __restrict__ B,
             const float* __restrict__ bias,
             float* __restrict__ C, int M, int N, int K) {
    __shared__ float As[2][64][AS_STRIDE];
    __shared__ float Bs[2][32][BS_STRIDE];

    const int tid  = threadIdx.x;
    const int warp = tid >> 5, lane = tid & 31;
    const int gq = lane >> 2, tq = lane & 3;
    const int wm = (warp & 1) * 32;
    const int wn = (warp >> 1) * 32;
    const int bm0 = blockIdx.y * 64;
    const int bn0 = blockIdx.x * 128;

    const float* Ag = A + (size_t)bm0 * K;
    const float* Bg = B + bn0;

    int arow[2], acol[2], brow[4], bcol[4];
    #pragma unroll
    for (int i = 0; i < 2; i++) {
        int c = tid + i * 256;
        arow[i] = c >> 3;  acol[i] = (c & 7) << 2;
    }
    #pragma unroll
    for (int i = 0; i < 4; i++) {
        int c = tid + i * 256;
        brow[i] = c >> 5;  bcol[i] = (c & 31) << 2;
    }

    auto load_stage = [&](int s, int kt) {
        const float* Agk = Ag + kt * 32;
        const float* Bgk = Bg + (size_t)kt * 32 * N;
        #pragma unroll
        for (int i = 0; i < 2; i++) {
            uint32_t sa = (uint32_t)__cvta_generic_to_shared(&As[s][arow[i]][acol[i]]);
            cp_async16(sa, Agk + (size_t)arow[i] * K + acol[i]);
        }
        #pragma unroll
        for (int i = 0; i < 4; i++) {
            uint32_t sb = (uint32_t)__cvta_generic_to_shared(&Bs[s][brow[i]][bcol[i]]);
            cp_async16(sb, Bgk + (size_t)brow[i] * N + bcol[i]);
        }
    };

    float c[2][4][4];
    #pragma unroll
    for (int i = 0; i < 2; i++)
        #pragma unroll
        for (int j = 0; j < 4; j++)
            #pragma unroll
            for (int k = 0; k < 4; k++) c[i][j][k] = 0.f;

    const int ntk = K >> 5;
    load_stage(0, 0); CP_COMMIT();

    for (int kt = 0; kt < ntk; kt++) {
        CP_WAIT0();
        __syncthreads();
        if (kt + 1 < ntk) { load_stage((kt + 1) & 1, kt + 1); CP_COMMIT(); }
        const int s = kt & 1;
        #pragma unroll
        for (int k0 = 0; k0 < 32; k0 += 8) {
            uint32_t af[2][4], bf[4][2];
            #pragma unroll
            for (int mt = 0; mt < 2; mt++) {
                const int r0 = wm + mt * 16 + gq;
                af[mt][0] = __float_as_uint(As[s][r0][k0 + tq]);
                af[mt][1] = __float_as_uint(As[s][r0 + 8][k0 + tq]);
                af[mt][2] = __float_as_uint(As[s][r0][k0 + tq + 4]);
                af[mt][3] = __float_as_uint(As[s][r0 + 8][k0 + tq + 4]);
            }
            #pragma unroll
            for (int nt = 0; nt < 4; nt++) {
                bf[nt][0] = __float_as_uint(Bs[s][k0 + tq][wn + nt * 8 + gq]);
                bf[nt][1] = __float_as_uint(Bs[s][k0 + tq + 4][wn + nt * 8 + gq]);
            }
            #pragma unroll
            for (int mt = 0; mt < 2; mt++)
                #pragma unroll
                for (int nt = 0; nt < 4; nt++)
                    mma_tf32(c[mt][nt], af[mt], bf[nt]);
        }
        __syncthreads();
    }

    #pragma unroll
    for (int mt = 0; mt < 2; mt++) {
        #pragma unroll
        for (int half = 0; half < 2; half++) {
            const int row = bm0 + wm + mt * 16 + gq + half * 8;
            #pragma unroll
            for (int nt = 0; nt < 4; nt++) {
                const int col = bn0 + wn + nt * 8 + 2 * tq;
                float2 r;
                r.x = c[mt][nt][half * 2 + 0];
                r.y = c[mt][nt][half * 2 + 1];
                float2 bv = *reinterpret_cast<const float2*>(bias + col);
                r.x += bv.x; r.y += bv.y;
                if (EPI == EPI_GELU) {
                    r.x = gelu_exact(r.x);
                    r.y = gelu_exact(r.y);
                }
                *reinterpret_cast<float2*>(C + (size_t)row * N + col) = r;
            }
        }
    }
}

// Split-K=2, 256-thread variant: writes raw partial (no bias).
__global__ __launch_bounds__(256)
void gemm_tc_sk(const float* __restrict__ A, const float* __restrict__ B,
                float* __restrict__ Cpart, int M, int N, int K) {
    __shared__ float As[2][64][AS_STRIDE];
    __shared__ float Bs[2][32][BS_STRIDE];

    const int tid  = threadIdx.x;
    const int warp = tid >> 5, lane = tid & 31;
    const int gq = lane >> 2, tq = lane & 3;
    const int wm = (warp & 1) * 32;
    const int wn = (warp >> 1) * 32;
    const int bm0 = blockIdx.y * 64;
    const int bn0 = blockIdx.x * 128;
    const int kz  = blockIdx.z;
    const int Kh  = K >> 1;

    const float* Ag = A + (size_t)bm0 * K + (size_t)kz * Kh;
    const float* Bg = B + bn0 + (size_t)kz * Kh * N;
    float* Cp = Cpart + (size_t)kz * M * N;

    int arow[2], acol[2], brow[4], bcol[4];
    #pragma unroll
    for (int i = 0; i < 2; i++) {
        int c = tid + i * 256;
        arow[i] = c >> 3;  acol[i] = (c & 7) << 2;
    }
    #pragma unroll
    for (int i = 0; i < 4; i++) {
        int c = tid + i * 256;
        brow[i] = c >> 5;  bcol[i] = (c & 31) << 2;
    }

    auto load_stage = [&](int s, int kt) {
        const float* Agk = Ag + kt * 32;
        const float* Bgk = Bg + (size_t)kt * 32 * N;
        #pragma unroll
        for (int i = 0; i < 2; i++) {
            uint32_t sa = (uint32_t)__cvta_generic_to_shared(&As[s][arow[i]][acol[i]]);
            cp_async16(sa, Agk + (size_t)arow[i] * K + acol[i]);
        }
        #pragma unroll
        for (int i = 0; i < 4; i++) {
            uint32_t sb = (uint32_t)__cvta_generic_to_shared(&Bs[s][brow[i]][bcol[i]]);
            cp_async16(sb, Bgk + (size_t)brow[i] * N + bcol[i]);
        }
    };

    float c[2][4][4];
    #pragma unroll
    for (int i = 0; i < 2; i++)
        #pragma unroll
        for (int j = 0; j < 4; j++)
            #pragma unroll
            for (int k = 0; k < 4; k++) c[i][j][k] = 0.f;

    const int ntk = Kh >> 5;
    load_stage(0, 0); CP_COMMIT();

    for (int kt = 0; kt < ntk; kt++) {
        CP_WAIT0();
        __syncthreads();
        if (kt + 1 < ntk) { load_stage((kt + 1) & 1, kt + 1); CP_COMMIT(); }
        const int s = kt & 1;
        #pragma unroll
        for (int k0 = 0; k0 < 32; k0 += 8) {
            uint32_t af[2][4], bf[4][2];
            #pragma unroll
            for (int mt = 0; mt < 2; mt++) {
                const int r0 = wm + mt * 16 + gq;
                af[mt][0] = __float_as_uint(As[s][r0][k0 + tq]);
                af[mt][1] = __float_as_uint(As[s][r0 + 8][k0 + tq]);
                af[mt][2] = __float_as_uint(As[s][r0][k0 + tq + 4]);
                af[mt][3] = __float_as_uint(As[s][r0 + 8][k0 + tq + 4]);
            }
            #pragma unroll
            for (int nt = 0; nt < 4; nt++) {
                bf[nt][0] = __float_as_uint(Bs[s][k0 + tq][wn + nt * 8 + gq]);
                bf[nt][1] = __float_as_uint(Bs[s][k0 + tq + 4][wn + nt * 8 + gq]);
            }
            #pragma unroll
            for (int mt = 0; mt < 2; mt++)
                #pragma unroll
                for (int nt = 0; nt < 4; nt++)
                    mma_tf32(c[mt][nt], af[mt], bf[nt]);
        }
        __syncthreads();
    }

    #pragma unroll
    for (int mt = 0; mt < 2; mt++)
        #pragma unroll
        for (int half = 0; half < 2; half++) {
            const int row = bm0 + wm + mt * 16 + gq + half * 8;
            #pragma unroll
            for (int nt = 0; nt < 4; nt++) {
                const int col = bn0 + wn + nt * 8 + 2 * tq;
                float2 r;
                r.x = c[mt][nt][half * 2 + 0];
                r.y = c[mt][nt][half * 2 + 1];
                *reinterpret_cast<float2*>(Cp + (size_t)row * N + col) = r;
            }
        }
}

// ------------- attention phase 1: tensor-core QK + joint partial dots -------
// grid (2 ktile, 2 qtile, NB*4), 128 threads. z = b*4 + kz (reduction quarter).
#define ZOFF ((size_t)NB*NC*NC)

__global__ __launch_bounds__(128)
void attn_scores_tc(const float* __restrict__ mask) {
    __shared__ float As[2][64][AS_STRIDE];
    __shared__ float Bs[2][64][AS_STRIDE];

    const int tid  = threadIdx.x;
    const int warp = tid >> 5, lane = tid & 31;
    const int gq = lane >> 2, tq = lane & 3;
    const int wm = (warp & 1) * 32;
    const int wn = (warp >> 1) * 32;
    const int k0g = blockIdx.x * 64;
    const int q0  = blockIdx.y * 64;
    const int b   = blockIdx.z >> 2;
    const int kz  = blockIdx.z & 3;

    const float* Qb = g_QKV + (size_t)(b*NC + q0)*3*ND + kz*128;
    const float* Kb = g_QKV + (size_t)(b*NC + k0g)*3*ND + ND + kz*128;
    const float* Mq = mask + (size_t)(b*NC + q0)*NL + kz*64;
    const float* Mk = mask + (size_t)(b*NC + k0g)*NL + kz*64;

    int rrow[4], rcol[4];
    #pragma unroll
    for (int i = 0; i < 4; i++) {
        int c = tid + i * 128;
        rrow[i] = c >> 3;  rcol[i] = (c & 7) << 2;
    }

    auto load_stage = [&](int g) {
        const int s = g & 1;
        if (g < 4) {
            const int off = g * 32;
            #pragma unroll
            for (int i = 0; i < 4; i++) {
                uint32_t sa = (uint32_t)__cvta_generic_to_shared(&As[s][rrow[i]][rcol[i]]);
                cp_async16(sa, Qb + (size_t)rrow[i] * 3*ND + off + rcol[i]);
                uint32_t sb = (uint32_t)__cvta_generic_to_shared(&Bs[s][rrow[i]][rcol[i]]);
                cp_async16(sb, Kb + (size_t)rrow[i] * 3*ND + off + rcol[i]);
            }
        } else {
            const int off = (g - 4) * 32;
            #pragma unroll
            for (int i = 0; i < 4; i++) {
                uint32_t sa = (uint32_t)__cvta_generic_to_shared(&As[s][rrow[i]][rcol[i]]);
                cp_async16(sa, Mq + (size_t)rrow[i] * NL + off + rcol[i]);
                uint32_t sb = (uint32_t)__cvta_generic_to_shared(&Bs[s][rrow[i]][rcol[i]]);
                cp_async16(sb, Mk + (size_t)rrow[i] * NL + off + rcol[i]);
            }
        }
    };

    float cS[2][4][4], cJ[2][4][4];
    #pragma unroll
    for (int i = 0; i < 2; i++)
        #pragma unroll
        for (int j = 0; j < 4; j++)
            #pragma unroll
            for (int k = 0; k < 4; k++) { cS[i][j][k] = 0.f; cJ[i][j][k] = 0.f; }

    load_stage(0); CP_COMMIT();

    #pragma unroll
    for (int g = 0; g < 6; g++) {
        CP_WAIT0();
        __syncthreads();
        if (g + 1 < 6) { load_stage(g + 1); CP_COMMIT(); }
        const int s = g & 1;
        #pragma unroll
        for (int k0 = 0; k0 < 32; k0 += 8) {
            uint32_t af[2][4], bf[4][2];
            #pragma unroll
            for (int mt = 0; mt < 2; mt++) {
                const int r0 = wm + mt * 16 + gq;
                af[mt][0] = __float_as_uint(As[s][r0][k0 + tq]);
                af[mt][1] = __float_as_uint(As[s][r0 + 8][k0 + tq]);
                af[mt][2] = __float_as_uint(As[s][r0][k0 + tq + 4]);
                af[mt][3] = __float_as_uint(As[s][r0 + 8][k0 + tq + 4]);
            }
            #pragma unroll
            for (int nt = 0; nt < 4; nt++) {
                bf[nt][0] = __float_as_uint(Bs[s][wn + nt * 8 + gq][k0 + tq]);
                bf[nt][1] = __float_as_uint(Bs[s][wn + nt * 8 + gq][k0 + tq + 4]);
            }
            if (g < 4) {
                #pragma unroll
                for (int mt = 0; mt < 2; mt++)
                    #pragma unroll
                    for (int nt = 0; nt < 4; nt++)
                        mma_tf32(cS[mt][nt], af[mt], bf[nt]);
            } else {
                #pragma unroll
                for (int mt = 0; mt < 2; mt++)
                    #pragma unroll
                    for (int nt = 0; nt < 4; nt++)
                        mma_tf32(cJ[mt][nt], af[mt], bf[nt]);
            }
        }
        __syncthreads();
    }

    #pragma unroll
    for (int mt = 0; mt < 2; mt++)
        #pragma unroll
        for (int half = 0; half < 2; half++) {
            const int row = q0 + wm + mt * 16 + gq + half * 8;
            #pragma unroll
            for (int nt = 0; nt < 4; nt++) {
                const int col = k0g + wn + nt * 8 + 2 * tq;
                const size_t idx = (size_t)kz*ZOFF + ((size_t)b*NC + row)*NC + col;
                float2 rs, rj;
                rs.x = cS[mt][nt][half*2 + 0]; rs.y = cS[mt][nt][half*2 + 1];
                rj.x = cJ[mt][nt][half*2 + 0]; rj.y = cJ[mt][nt][half*2 + 1];
                *reinterpret_cast<float2*>(g_Sp + idx) = rs;
                *reinterpret_cast<float2*>(g_Jp + idx) = rj;
            }
        }
}

// ---------------- attention phase 2: modulate + softmax + AV ----------------
__global__ __launch_bounds__(128)
void attn_av(const float* __restrict__ unused) {
    __shared__ float S_sh[8*128];
    __shared__ float v_sh[16*260];

    const int b   = blockIdx.y;
    const int c0  = blockIdx.x * 8;
    const int z   = blockIdx.z;          // output dim half
    const int tid = threadIdx.x;
    const float scale = 0.04419417382415922f;

    {
        const int row = tid >> 4;
        const int sub = tid & 15;
        const size_t base = ((size_t)b*NC + c0 + row)*NC;
        const float tq = g_total[b*NC + c0 + row];
        float v[8];
        float mx = -1e30f;
        #pragma unroll
        for (int i = 0; i < 8; i++) {
            const int e = sub + 16*i;
            float a  = (g_Sp[base + e] + g_Sp[ZOFF + base + e])
                     + (g_Sp[2*ZOFF + base + e] + g_Sp[3*ZOFF + base + e]);
            float jj = (g_Jp[base + e] + g_Jp[ZOFF + base + e])
                     + (g_Jp[2*ZOFF + base + e] + g_Jp[3*ZOFF + base + e]);
            float tk = g_total[b*NC + e];
            float ov = 2.0f * jj / fmaxf(tq + tk, 1.0f);
            v[i] = a * scale * (0.5f + 0.5f * ov);
            mx = fmaxf(mx, v[i]);
        }
        #pragma unroll
        for (int m = 1; m < 16; m <<= 1)
            mx = fmaxf(mx, __shfl_xor_sync(0xffffffffu, mx, m));
        float sm = 0.f;
        #pragma unroll
        for (int i = 0; i < 8; i++) { v[i] = expf(v[i] - mx); sm += v[i]; }
        #pragma unroll
        for (int m = 1; m < 16; m <<= 1)
            sm += __shfl_xor_sync(0xffffffffu, sm, m);
        const float inv = 1.0f / sm;
        #pragma unroll
        for (int i = 0; i < 8; i++)
            S_sh[row*128 + sub + 16*i] = v[i] * inv;
    }
    __syncthreads();

    float2 o[8];
    #pragma unroll
    for (int r = 0; r < 8; r++) o[r] = make_float2(0.f, 0.f);
    const int d0 = tid * 2;

    for (int ch = 0; ch < 8; ch++) {
        #pragma unroll
        for (int i = 0; i < 8; i++) {
            int c = tid + i * 128;
            int r = c >> 6, col = (c & 63) << 2;
            float4 v = *reinterpret_cast<const float4*>(
                g_QKV + (size_t)(b*NC + ch*16 + r)*3*ND + 2*ND + z*256 + col);
            *reinterpret_cast<float4*>(v_sh + r*260 + col) = v;
        }
        __syncthreads();
        #pragma unroll
        for (int ee = 0; ee < 16; ee++) {
            float2 v2 = *reinterpret_cast<const float2*>(v_sh + ee*260 + d0);
            const int eg = ch*16 + ee;
            #pragma unroll
            for (int r = 0; r < 8; r++) {
                float a = S_sh[r*128 + eg];
                o[r].x += a*v2.x; o[r].y += a*v2.y;
            }
        }
        __syncthreads();
    }

    #pragma unroll
    for (int r = 0; r < 8; r++) {
        float2 t;
        t.x = o[r].x; t.y = o[r].y;
        *reinterpret_cast<float2*>(g_ctx + (size_t)(b*NC + c0 + r)*ND + z*256 + d0) = t;
    }
}

// ------------- LayerNorm combine: v = P0 + P1 + bias + Res, then LN ---------
__global__ __launch_bounds__(128)
void ln_comb_kernel(const float* __restrict__ P,
                    const float* __restrict__ Res,
                    const float* __restrict__ bias,
                    const float* __restrict__ g, const float* __restrict__ be,
                    float* __restrict__ out) {
    const int row = blockIdx.x;
    const int tid = threadIdx.x;   // 128
    __shared__ float red_s[128];
    __shared__ float red_q[128];

    const size_t idx = (size_t)row*(ND/4) + tid;
    float4 p0 = reinterpret_cast<const float4*>(P)[idx];
    float4 p1 = reinterpret_cast<const float4*>(P + (size_t)ROWS*ND)[idx];
    float4 rs = reinterpret_cast<const float4*>(Res)[idx];
    float4 bb = reinterpret_cast<const float4*>(bias)[tid];
    float4 v;
    v.x = p0.x + p1.x + bb.x + rs.x;
    v.y = p0.y + p1.y + bb.y + rs.y;
    v.z = p0.z + p1.z + bb.z + rs.z;
    v.w = p0.w + p1.w + bb.w + rs.w;

    float s  = v.x + v.y + v.z + v.w;
    float sq = v.x*v.x + v.y*v.y + v.z*v.z + v.w*v.w;
    red_s[tid] = s; red_q[tid] = sq;
    __syncthreads();
    #pragma unroll
    for (int st = 64; st > 0; st >>= 1) {
        if (tid < st) { red_s[tid] += red_s[tid+st]; red_q[tid] += red_q[tid+st]; }
        __syncthreads();
    }
    const float mean = red_s[0] * (1.0f/ND);
    const float var  = red_q[0] * (1.0f/ND) - mean*mean;
    const float inv  = rsqrtf(var + 1e-5f);

    float4 g4 = reinterpret_cast<const float4*>(g)[tid];
    float4 b4 = reinterpret_cast<const float4*>(be)[tid];
    float4 r;
    r.x = (v.x - mean)*inv*g4.x + b4.x;
    r.y = (v.y - mean)*inv*g4.y + b4.y;
    r.z = (v.z - mean)*inv*g4.z + b4.z;
    r.w = (v.w - mean)*inv*g4.w + b4.w;
    reinterpret_cast<float4*>(out)[idx] = r;
}

// ---------------- launch ----------------------------------------------------
extern "C" void kernel_launch(void* const* d_in, const int* in_sizes, int n_in,
                              void* d_out, int out_size) {
    const float* x    = (const float*)d_in[0];
    const float* mask = (const float*)d_in[1];
    const float* Wqkv = (const float*)d_in[2];
    const float* bqkv = (const float*)d_in[3];
    const float* Wo   = (const float*)d_in[4];
    const float* bo   = (const float*)d_in[5];
    const float* W1   = (const float*)d_in[6];
    const float* b1   = (const float*)d_in[7];
    const float* W2   = (const float*)d_in[8];
    const float* b2   = (const float*)d_in[9];
    const float* g1   = (const float*)d_in[10];
    const float* be1  = (const float*)d_in[11];
    const float* g2   = (const float*)d_in[12];
    const float* be2  = (const float*)d_in[13];
    float* out = (float*)d_out;

    float *E0, *QKV, *ctx, *P, *E1, *H;
    float *Wqkv_tf, *Wo_tf, *W1_tf, *W2_tf;
    cudaGetSymbolAddress((void**)&E0,   g_E0);
    cudaGetSymbolAddress((void**)&QKV,  g_QKV);
    cudaGetSymbolAddress((void**)&ctx,  g_ctx);
    cudaGetSymbolAddress((void**)&P,    g_P);
    cudaGetSymbolAddress((void**)&E1,   g_E1);
    cudaGetSymbolAddress((void**)&H,    g_H);
    cudaGetSymbolAddress((void**)&Wqkv_tf, g_Wqkv);
    cudaGetSymbolAddress((void**)&Wo_tf,   g_Wo);
    cudaGetSymbolAddress((void**)&W1_tf,   g_W1);
    cudaGetSymbolAddress((void**)&W2_tf,   g_W2);

    // Side stream: ONLY the tiny weight-conversion overlapped under the
    // memory-bound pool. Created per call; graph replays are free.
    cudaStream_t s1;
    cudaStreamCreateWithFlags(&s1, cudaStreamNonBlocking);
    cudaEvent_t evFork, evCvt;
    cudaEventCreateWithFlags(&evFork, cudaEventDisableTiming);
    cudaEventCreateWithFlags(&evCvt,  cudaEventDisableTiming);

    cudaEventRecord(evFork, 0);
    cudaStreamWaitEvent(s1, evFork, 0);
    cvt_all_kernel<<<(NW_QKV+NW_O+NW_1+NW_2)/256, 256, 0, s1>>>(Wqkv, Wo, W1, W2);
    cudaEventRecord(evCvt, s1);

    // s0: masked mean pool (HBM-bound)
    pool_kernel<<<ROWS, 128>>>(x, mask);
    cudaStreamWaitEvent(0, evCvt, 0);

    // QKV = E0 @ Wqkv + bqkv     (2048 x 1536 x 512), A = raw fp32
    gemm_tc<EPI_BIAS><<<dim3(3*ND/128, ROWS/64), 256>>>(E0, Wqkv_tf, bqkv, QKV, ROWS, 3*ND, ND);

    // attention partial dots (4 split-K quarters)
    attn_scores_tc<<<dim3(2, 2, NB*4), 128>>>(mask);
    // modulate + softmax + AV (dim-half split)
    attn_av<<<dim3(NC/8, NB, 2), 128>>>(mask);

    // P = ctx @ Wo (split-K=2 partials)   (2048 x 512 x 512)
    gemm_tc_sk<<<dim3(ND/128, ROWS/64, 2), 256>>>(ctx, Wo_tf, P, ROWS, ND, ND);

    // E1 = LN(P0+P1+bo+E0)
    ln_comb_kernel<<<ROWS, 128>>>(P, E0, bo, g1, be1, E1);

    // H = gelu(E1 @ W1 + b1)     (2048 x 1024 x 512)
    gemm_tc<EPI_GELU><<<dim3(2*ND/128, ROWS/64), 256>>>(E1, W1_tf, b1, H, ROWS, 2*ND, ND);

    // P = H @ W2 (split-K=2 partials)     (2048 x 512 x 1024)
    gemm_tc_sk<<<dim3(ND/128, ROWS/64, 2), 256>>>(H, W2_tf, P, ROWS, ND, 2*ND);

    // out = LN(P0+P1+b2+E1)
    ln_comb_kernel<<<ROWS, 128>>>(P, E1, b2, g2, be2, out);

    cudaEventDestroy(evFork);
    cudaEventDestroy(evCvt);
    cudaStreamDestroy(s1);
}

// round 16
// speedup vs baseline: 1.0301x; 1.0234x over previous
#include <cuda_runtime.h>
#include <math.h>
#include <stdint.h>

#define NB 16
#define NC 128
#define NL 256
#define ND 512
#define ROWS (NB*NC)   // 2048

// ---------------- scratch (no allocations allowed) ----------------
__device__ float g_E0[ROWS*ND];
__device__ float g_total[ROWS];
__device__ float g_QKV[ROWS*3*ND];
__device__ float g_ctx[ROWS*ND];
__device__ float g_Sp[4*NB*NC*NC];     // QK partial dots (4 split-K quarters)
__device__ float g_Jp[4*NB*NC*NC];     // mask-joint partial dots
__device__ float g_A[NB*NC*NC];        // softmax probabilities (tf32-rounded)
__device__ float g_P[2*ROWS*ND];
__device__ float g_E1[ROWS*ND];
__device__ float g_H[ROWS*2*ND];
__device__ float g_Wqkv[ND*3*ND];
__device__ float g_Wo[ND*ND];
__device__ float g_W1[ND*2*ND];
__device__ float g_W2[2*ND*ND];

__device__ __forceinline__ uint32_t f2tf(float f) {
    uint32_t u;
    asm("cvt.rna.tf32.f32 %0, %1;" : "=r"(u) : "f"(f));
    return u;
}
__device__ __forceinline__ float f2tf_f(float f) { return __uint_as_float(f2tf(f)); }

// ---------------- fused weight converter ----------------
#define NW_QKV (ND*3*ND/4)
#define NW_O   (ND*ND/4)
#define NW_1   (ND*2*ND/4)
#define NW_2   (2*ND*ND/4)
__global__ void cvt_all_kernel(const float* __restrict__ wqkv, const float* __restrict__ wo,
                               const float* __restrict__ w1, const float* __restrict__ w2) {
    int i = blockIdx.x * blockDim.x + threadIdx.x;
    const float4* src; float4* dst; int off;
    if (i < NW_QKV)                 { src = (const float4*)wqkv; dst = (float4*)g_Wqkv; off = i; }
    else if (i < NW_QKV+NW_O)       { src = (const float4*)wo;   dst = (float4*)g_Wo;   off = i - NW_QKV; }
    else if (i < NW_QKV+NW_O+NW_1)  { src = (const float4*)w1;   dst = (float4*)g_W1;   off = i - NW_QKV - NW_O; }
    else                            { src = (const float4*)w2;   dst = (float4*)g_W2;   off = i - NW_QKV - NW_O - NW_1; }
    float4 v = src[off];
    v.x = f2tf_f(v.x); v.y = f2tf_f(v.y); v.z = f2tf_f(v.z); v.w = f2tf_f(v.w);
    dst[off] = v;
}

// ---------------- masked mean pool ----------------
__global__ void pool_kernel(const float* __restrict__ x,
                            const float* __restrict__ mask) {
    const int row = blockIdx.x;
    const int tid = threadIdx.x;          // 128 threads
    __shared__ float msh[NL];
    __shared__ float red[128];

    float m0 = mask[(size_t)row*NL + tid];
    float m1 = mask[(size_t)row*NL + 128 + tid];
    msh[tid] = m0; msh[tid + 128] = m1;
    red[tid] = m0 + m1;
    __syncthreads();
    #pragma unroll
    for (int s = 64; s > 0; s >>= 1) {
        if (tid < s) red[tid] += red[tid + s];
        __syncthreads();
    }
    const float msum = red[0];

    const float4* xr = reinterpret_cast<const float4*>(x) + (size_t)row*NL*(ND/4);
    float4 acc = make_float4(0.f,0.f,0.f,0.f);
    #pragma unroll 8
    for (int l = 0; l < NL; l++) {
        float4 v = __ldcs(&xr[(size_t)l*(ND/4) + tid]);
        float m = msh[l];
        acc.x += v.x*m; acc.y += v.y*m; acc.z += v.z*m; acc.w += v.w*m;
    }
    const float inv = 1.0f / fmaxf(msum, 1.0f);
    acc.x *= inv; acc.y *= inv; acc.z *= inv; acc.w *= inv;
    reinterpret_cast<float4*>(g_E0)[(size_t)row*(ND/4) + tid] = acc;
    if (tid == 0) g_total[row] = msum;
}

// ---------------- TF32 tensor-core GEMM core ---------------------------------
#define EPI_BIAS 0
#define EPI_GELU 2

__device__ __forceinline__ float gelu_exact(float v) {
    return 0.5f * v * (1.0f + erff(v * 0.70710678118654752f));
}

__device__ __forceinline__ void mma_tf32(float* c, const uint32_t* a, const uint32_t* b) {
    asm volatile(
        "mma.sync.aligned.m16n8k8.row.col.f32.tf32.tf32.f32 "
        "{%0,%1,%2,%3}, {%4,%5,%6,%7}, {%8,%9}, {%0,%1,%2,%3};\n"
        : "+f"(c[0]), "+f"(c[1]), "+f"(c[2]), "+f"(c[3])
        : "r"(a[0]), "r"(a[1]), "r"(a[2]), "r"(a[3]),
          "r"(b[0]), "r"(b[1]));
}

__device__ __forceinline__ void cp_async16(uint32_t saddr, const void* g) {
    asm volatile("cp.async.cg.shared.global [%0], [%1], 16;\n" :: "r"(saddr), "l"(g));
}
#define CP_COMMIT() asm volatile("cp.async.commit_group;\n" ::: "memory")
#define CP_WAIT0()  asm volatile("cp.async.wait_group 0;\n" ::: "memory")

#define AS_STRIDE 36
#define BS_STRIDE 136
#define BS64_STRIDE 72

// ---- 256-thread GEMM: BM=64, BN=128, BK=32; 8 warps 2(m)x4(n).
// A operand is raw fp32 (HW RZ-truncates to tf32); B is rna-preconverted.
template<int EPI>
__global__ __launch_bounds__(256)
void gemm_tc(const float* __restrict__ A, const float* __restrict__ B,
             const float* __restrict__ bias,
             float* __restrict__ C, int M, int N, int K) {
    __shared__ float As[2][64][AS_STRIDE];
    __shared__ float Bs[2][32][BS_STRIDE];

    const int tid  = threadIdx.x;
    const int warp = tid >> 5, lane = tid & 31;
    const int gq = lane >> 2, tq = lane & 3;
    const int wm = (warp & 1) * 32;
    const int wn = (warp >> 1) * 32;
    const int bm0 = blockIdx.y * 64;
    const int bn0 = blockIdx.x * 128;

    const float* Ag = A + (size_t)bm0 * K;
    const float* Bg = B + bn0;

    int arow[2], acol[2], brow[4], bcol[4];
    #pragma unroll
    for (int i = 0; i < 2; i++) {
        int c = tid + i * 256;
        arow[i] = c >> 3;  acol[i] = (c & 7) << 2;
    }
    #pragma unroll
    for (int i = 0; i < 4; i++) {
        int c = tid + i * 256;
        brow[i] = c >> 5;  bcol[i] = (c & 31) << 2;
    }

    auto load_stage = [&](int s, int kt) {
        const float* Agk = Ag + kt * 32;
        const float* Bgk = Bg + (size_t)kt * 32 * N;
        #pragma unroll
        for (int i = 0; i < 2; i++) {
            uint32_t sa = (uint32_t)__cvta_generic_to_shared(&As[s][arow[i]][acol[i]]);
            cp_async16(sa, Agk + (size_t)arow[i] * K + acol[i]);
        }
        #pragma unroll
        for (int i = 0; i < 4; i++) {
            uint32_t sb = (uint32_t)__cvta_generic_to_shared(&Bs[s][brow[i]][bcol[i]]);
            cp_async16(sb, Bgk + (size_t)brow[i] * N + bcol[i]);
        }
    };

    float c[2][4][4];
    #pragma unroll
    for (int i = 0; i < 2; i++)
        #pragma unroll
        for (int j = 0; j < 4; j++)
            #pragma unroll
            for (int k = 0; k < 4; k++) c[i][j][k] = 0.f;

    const int ntk = K >> 5;
    load_stage(0, 0); CP_COMMIT();

    for (int kt = 0; kt < ntk; kt++) {
        CP_WAIT0();
        __syncthreads();
        if (kt + 1 < ntk) { load_stage((kt + 1) & 1, kt + 1); CP_COMMIT(); }
        const int s = kt & 1;
        #pragma unroll
        for (int k0 = 0; k0 < 32; k0 += 8) {
            uint32_t af[2][4], bf[4][2];
            #pragma unroll
            for (int mt = 0; mt < 2; mt++) {
                const int r0 = wm + mt * 16 + gq;
                af[mt][0] = __float_as_uint(As[s][r0][k0 + tq]);
                af[mt][1] = __float_as_uint(As[s][r0 + 8][k0 + tq]);
                af[mt][2] = __float_as_uint(As[s][r0][k0 + tq + 4]);
                af[mt][3] = __float_as_uint(As[s][r0 + 8][k0 + tq + 4]);
            }
            #pragma unroll
            for (int nt = 0; nt < 4; nt++) {
                bf[nt][0] = __float_as_uint(Bs[s][k0 + tq][wn + nt * 8 + gq]);
                bf[nt][1] = __float_as_uint(Bs[s][k0 + tq + 4][wn + nt * 8 + gq]);
            }
            #pragma unroll
            for (int mt = 0; mt < 2; mt++)
                #pragma unroll
                for (int nt = 0; nt < 4; nt++)
                    mma_tf32(c[mt][nt], af[mt], bf[nt]);
        }
        __syncthreads();
    }

    #pragma unroll
    for (int mt = 0; mt < 2; mt++) {
        #pragma unroll
        for (int half = 0; half < 2; half++) {
            const int row = bm0 + wm + mt * 16 + gq + half * 8;
            #pragma unroll
            for (int nt = 0; nt < 4; nt++) {
                const int col = bn0 + wn + nt * 8 + 2 * tq;
                float2 r;
                r.x = c[mt][nt][half * 2 + 0];
                r.y = c[mt][nt][half * 2 + 1];
                float2 bv = *reinterpret_cast<const float2*>(bias + col);
                r.x += bv.x; r.y += bv.y;
                if (EPI == EPI_GELU) {
                    r.x = gelu_exact(r.x);
                    r.y = gelu_exact(r.y);
                }
                *reinterpret_cast<float2*>(C + (size_t)row * N + col) = r;
            }
        }
    }
}

// Split-K=2, 256-thread variant: writes raw partial (no bias).
__global__ __launch_bounds__(256)
void gemm_tc_sk(const float* __restrict__ A, const float* __restrict__ B,
                float* __restrict__ Cpart, int M, int N, int K) {
    __shared__ float As[2][64][AS_STRIDE];
    __shared__ float Bs[2][32][BS_STRIDE];

    const int tid  = threadIdx.x;
    const int warp = tid >> 5, lane = tid & 31;
    const int gq = lane >> 2, tq = lane & 3;
    const int wm = (warp & 1) * 32;
    const int wn = (warp >> 1) * 32;
    const int bm0 = blockIdx.y * 64;
    const int bn0 = blockIdx.x * 128;
    const int kz  = blockIdx.z;
    const int Kh  = K >> 1;

    const float* Ag = A + (size_t)bm0 * K + (size_t)kz * Kh;
    const float* Bg = B + bn0 + (size_t)kz * Kh * N;
    float* Cp = Cpart + (size_t)kz * M * N;

    int arow[2], acol[2], brow[4], bcol[4];
    #pragma unroll
    for (int i = 0; i < 2; i++) {
        int c = tid + i * 256;
        arow[i] = c >> 3;  acol[i] = (c & 7) << 2;
    }
    #pragma unroll
    for (int i = 0; i < 4; i++) {
        int c = tid + i * 256;
        brow[i] = c >> 5;  bcol[i] = (c & 31) << 2;
    }

    auto load_stage = [&](int s, int kt) {
        const float* Agk = Ag + kt * 32;
        const float* Bgk = Bg + (size_t)kt * 32 * N;
        #pragma unroll
        for (int i = 0; i < 2; i++) {
            uint32_t sa = (uint32_t)__cvta_generic_to_shared(&As[s][arow[i]][acol[i]]);
            cp_async16(sa, Agk + (size_t)arow[i] * K + acol[i]);
        }
        #pragma unroll
        for (int i = 0; i < 4; i++) {
            uint32_t sb = (uint32_t)__cvta_generic_to_shared(&Bs[s][brow[i]][bcol[i]]);
            cp_async16(sb, Bgk + (size_t)brow[i] * N + bcol[i]);
        }
    };

    float c[2][4][4];
    #pragma unroll
    for (int i = 0; i < 2; i++)
        #pragma unroll
        for (int j = 0; j < 4; j++)
            #pragma unroll
            for (int k = 0; k < 4; k++) c[i][j][k] = 0.f;

    const int ntk = Kh >> 5;
    load_stage(0, 0); CP_COMMIT();

    for (int kt = 0; kt < ntk; kt++) {
        CP_WAIT0();
        __syncthreads();
        if (kt + 1 < ntk) { load_stage((kt + 1) & 1, kt + 1); CP_COMMIT(); }
        const int s = kt & 1;
        #pragma unroll
        for (int k0 = 0; k0 < 32; k0 += 8) {
            uint32_t af[2][4], bf[4][2];
            #pragma unroll
            for (int mt = 0; mt < 2; mt++) {
                const int r0 = wm + mt * 16 + gq;
                af[mt][0] = __float_as_uint(As[s][r0][k0 + tq]);
                af[mt][1] = __float_as_uint(As[s][r0 + 8][k0 + tq]);
                af[mt][2] = __float_as_uint(As[s][r0][k0 + tq + 4]);
                af[mt][3] = __float_as_uint(As[s][r0 + 8][k0 + tq + 4]);
            }
            #pragma unroll
            for (int nt = 0; nt < 4; nt++) {
                bf[nt][0] = __float_as_uint(Bs[s][k0 + tq][wn + nt * 8 + gq]);
                bf[nt][1] = __float_as_uint(Bs[s][k0 + tq + 4][wn + nt * 8 + gq]);
            }
            #pragma unroll
            for (int mt = 0; mt < 2; mt++)
                #pragma unroll
                for (int nt = 0; nt < 4; nt++)
                    mma_tf32(c[mt][nt], af[mt], bf[nt]);
        }
        __syncthreads();
    }

    #pragma unroll
    for (int mt = 0; mt < 2; mt++)
        #pragma unroll
        for (int half = 0; half < 2; half++) {
            const int row = bm0 + wm + mt * 16 + gq + half * 8;
            #pragma unroll
            for (int nt = 0; nt < 4; nt++) {
                const int col = bn0 + wn + nt * 8 + 2 * tq;
                float2 r;
                r.x = c[mt][nt][half * 2 + 0];
                r.y = c[mt][nt][half * 2 + 1];
                *reinterpret_cast<float2*>(Cp + (size_t)row * N + col) = r;
            }
        }
}

// ------------- attention phase 1: tensor-core QK + joint partial dots -------
// grid (2 ktile, 2 qtile, NB*4), 128 threads. z = b*4 + kz (reduction quarter).
#define ZOFF ((size_t)NB*NC*NC)

__global__ __launch_bounds__(128)
void attn_scores_tc(const float* __restrict__ mask) {
    __shared__ float As[2][64][AS_STRIDE];
    __shared__ float Bs[2][64][AS_STRIDE];

    const int tid  = threadIdx.x;
    const int warp = tid >> 5, lane = tid & 31;
    const int gq = lane >> 2, tq = lane & 3;
    const int wm = (warp & 1) * 32;
    const int wn = (warp >> 1) * 32;
    const int k0g = blockIdx.x * 64;
    const int q0  = blockIdx.y * 64;
    const int b   = blockIdx.z >> 2;
    const int kz  = blockIdx.z & 3;

    const float* Qb = g_QKV + (size_t)(b*NC + q0)*3*ND + kz*128;
    const float* Kb = g_QKV + (size_t)(b*NC + k0g)*3*ND + ND + kz*128;
    const float* Mq = mask + (size_t)(b*NC + q0)*NL + kz*64;
    const float* Mk = mask + (size_t)(b*NC + k0g)*NL + kz*64;

    int rrow[4], rcol[4];
    #pragma unroll
    for (int i = 0; i < 4; i++) {
        int c = tid + i * 128;
        rrow[i] = c >> 3;  rcol[i] = (c & 7) << 2;
    }

    auto load_stage = [&](int g) {
        const int s = g & 1;
        if (g < 4) {
            const int off = g * 32;
            #pragma unroll
            for (int i = 0; i < 4; i++) {
                uint32_t sa = (uint32_t)__cvta_generic_to_shared(&As[s][rrow[i]][rcol[i]]);
                cp_async16(sa, Qb + (size_t)rrow[i] * 3*ND + off + rcol[i]);
                uint32_t sb = (uint32_t)__cvta_generic_to_shared(&Bs[s][rrow[i]][rcol[i]]);
                cp_async16(sb, Kb + (size_t)rrow[i] * 3*ND + off + rcol[i]);
            }
        } else {
            const int off = (g - 4) * 32;
            #pragma unroll
            for (int i = 0; i < 4; i++) {
                uint32_t sa = (uint32_t)__cvta_generic_to_shared(&As[s][rrow[i]][rcol[i]]);
                cp_async16(sa, Mq + (size_t)rrow[i] * NL + off + rcol[i]);
                uint32_t sb = (uint32_t)__cvta_generic_to_shared(&Bs[s][rrow[i]][rcol[i]]);
                cp_async16(sb, Mk + (size_t)rrow[i] * NL + off + rcol[i]);
            }
        }
    };

    float cS[2][4][4], cJ[2][4][4];
    #pragma unroll
    for (int i = 0; i < 2; i++)
        #pragma unroll
        for (int j = 0; j < 4; j++)
            #pragma unroll
            for (int k = 0; k < 4; k++) { cS[i][j][k] = 0.f; cJ[i][j][k] = 0.f; }

    load_stage(0); CP_COMMIT();

    #pragma unroll
    for (int g = 0; g < 6; g++) {
        CP_WAIT0();
        __syncthreads();
        if (g + 1 < 6) { load_stage(g + 1); CP_COMMIT(); }
        const int s = g & 1;
        #pragma unroll
        for (int k0 = 0; k0 < 32; k0 += 8) {
            uint32_t af[2][4], bf[4][2];
            #pragma unroll
            for (int mt = 0; mt < 2; mt++) {
                const int r0 = wm + mt * 16 + gq;
                af[mt][0] = __float_as_uint(As[s][r0][k0 + tq]);
                af[mt][1] = __float_as_uint(As[s][r0 + 8][k0 + tq]);
                af[mt][2] = __float_as_uint(As[s][r0][k0 + tq + 4]);
                af[mt][3] = __float_as_uint(As[s][r0 + 8][k0 + tq + 4]);
            }
            #pragma unroll
            for (int nt = 0; nt < 4; nt++) {
                bf[nt][0] = __float_as_uint(Bs[s][wn + nt * 8 + gq][k0 + tq]);
                bf[nt][1] = __float_as_uint(Bs[s][wn + nt * 8 + gq][k0 + tq + 4]);
            }
            if (g < 4) {
                #pragma unroll
                for (int mt = 0; mt < 2; mt++)
                    #pragma unroll
                    for (int nt = 0; nt < 4; nt++)
                        mma_tf32(cS[mt][nt], af[mt], bf[nt]);
            } else {
                #pragma unroll
                for (int mt = 0; mt < 2; mt++)
                    #pragma unroll
                    for (int nt = 0; nt < 4; nt++)
                        mma_tf32(cJ[mt][nt], af[mt], bf[nt]);
            }
        }
        __syncthreads();
    }

    #pragma unroll
    for (int mt = 0; mt < 2; mt++)
        #pragma unroll
        for (int half = 0; half < 2; half++) {
            const int row = q0 + wm + mt * 16 + gq + half * 8;
            #pragma unroll
            for (int nt = 0; nt < 4; nt++) {
                const int col = k0g + wn + nt * 8 + 2 * tq;
                const size_t idx = (size_t)kz*ZOFF + ((size_t)b*NC + row)*NC + col;
                float2 rs, rj;
                rs.x = cS[mt][nt][half*2 + 0]; rs.y = cS[mt][nt][half*2 + 1];
                rj.x = cJ[mt][nt][half*2 + 0]; rj.y = cJ[mt][nt][half*2 + 1];
                *reinterpret_cast<float2*>(g_Sp + idx) = rs;
                *reinterpret_cast<float2*>(g_Jp + idx) = rj;
            }
        }
}

// ---------------- attention phase 2a: modulate + softmax -> g_A -------------
// grid (16 q-tiles, 16 batches), 128 threads.
__global__ __launch_bounds__(128)
void attn_softmax(const float* __restrict__ unused) {
    __shared__ float S_sh[8*128];

    const int b   = blockIdx.y;
    const int c0  = blockIdx.x * 8;
    const int tid = threadIdx.x;
    const float scale = 0.04419417382415922f;

    {
        const int row = tid >> 4;
        const int sub = tid & 15;
        const size_t base = ((size_t)b*NC + c0 + row)*NC;
        const float tq = g_total[b*NC + c0 + row];
        float v[8];
        float mx = -1e30f;
        #pragma unroll
        for (int i = 0; i < 8; i++) {
            const int e = sub + 16*i;
            float a  = (g_Sp[base + e] + g_Sp[ZOFF + base + e])
                     + (g_Sp[2*ZOFF + base + e] + g_Sp[3*ZOFF + base + e]);
            float jj = (g_Jp[base + e] + g_Jp[ZOFF + base + e])
                     + (g_Jp[2*ZOFF + base + e] + g_Jp[3*ZOFF + base + e]);
            float tk = g_total[b*NC + e];
            float ov = 2.0f * jj / fmaxf(tq + tk, 1.0f);
            v[i] = a * scale * (0.5f + 0.5f * ov);
            mx = fmaxf(mx, v[i]);
        }
        #pragma unroll
        for (int m = 1; m < 16; m <<= 1)
            mx = fmaxf(mx, __shfl_xor_sync(0xffffffffu, mx, m));
        float sm = 0.f;
        #pragma unroll
        for (int i = 0; i < 8; i++) { v[i] = expf(v[i] - mx); sm += v[i]; }
        #pragma unroll
        for (int m = 1; m < 16; m <<= 1)
            sm += __shfl_xor_sync(0xffffffffu, sm, m);
        const float inv = 1.0f / sm;
        #pragma unroll
        for (int i = 0; i < 8; i++)
            S_sh[row*128 + sub + 16*i] = f2tf_f(v[i] * inv);   // rna: no RZ bias
    }
    __syncthreads();

    // coalesced writeout: 8x128 = 256 float4, 2 per thread
    #pragma unroll
    for (int i = 0; i < 2; i++) {
        int c = tid + i * 128;
        int r = c >> 5, col = (c & 31) << 2;
        float4 v = *reinterpret_cast<const float4*>(S_sh + r*128 + col);
        *reinterpret_cast<float4*>(g_A + ((size_t)b*NC + c0 + r)*NC + col) = v;
    }
}

// ---------------- attention phase 2b: AV on tensor cores --------------------
// ctx[b] = A[b](128x128) @ V[b](128x512). 128 threads, BM=BN=64, BK=32,
// 4 warps 2x2, 4 K-tiles. Same fragment math as gemm_tc (proven layout).
__global__ __launch_bounds__(128)
void attn_av_tc(const float* __restrict__ unused) {
    __shared__ float As[2][64][AS_STRIDE];
    __shared__ float Bs[2][32][BS64_STRIDE];

    const int tid  = threadIdx.x;
    const int warp = tid >> 5, lane = tid & 31;
    const int gq = lane >> 2, tq = lane & 3;
    const int wm = (warp & 1) * 32;
    const int wn = (warp >> 1) * 32;
    const int n0 = blockIdx.x * 64;    // dim tile
    const int m0 = blockIdx.y * 64;    // query tile
    const int b  = blockIdx.z;

    const float* Ag = g_A + (size_t)b*NC*NC + (size_t)m0*NC;
    const float* Vg = g_QKV + (size_t)(b*NC)*3*ND + 2*ND + n0;

    int arow[4], acol[4], brow[4], bcol[4];
    #pragma unroll
    for (int i = 0; i < 4; i++) {
        int c = tid + i * 128;
        arow[i] = c >> 3;  acol[i] = (c & 7) << 2;   // 64 x 32
        brow[i] = c >> 4;  bcol[i] = (c & 15) << 2;  // 32 x 64
    }

    auto load_stage = [&](int s, int kt) {
        const float* Agk = Ag + kt * 32;
        const float* Vgk = Vg + (size_t)(kt * 32) * 3*ND;
        #pragma unroll
        for (int i = 0; i < 4; i++) {
            uint32_t sa = (uint32_t)__cvta_generic_to_shared(&As[s][arow[i]][acol[i]]);
            cp_async16(sa, Agk + (size_t)arow[i] * NC + acol[i]);
        }
        #pragma unroll
        for (int i = 0; i < 4; i++) {
            uint32_t sb = (uint32_t)__cvta_generic_to_shared(&Bs[s][brow[i]][bcol[i]]);
            cp_async16(sb, Vgk + (size_t)brow[i] * 3*ND + bcol[i]);
        }
    };

    float c[2][4][4];
    #pragma unroll
    for (int i = 0; i < 2; i++)
        #pragma unroll
        for (int j = 0; j < 4; j++)
            #pragma unroll
            for (int k = 0; k < 4; k++) c[i][j][k] = 0.f;

    load_stage(0, 0); CP_COMMIT();

    #pragma unroll
    for (int kt = 0; kt < 4; kt++) {
        CP_WAIT0();
        __syncthreads();
        if (kt + 1 < 4) { load_stage((kt + 1) & 1, kt + 1); CP_COMMIT(); }
        const int s = kt & 1;
        #pragma unroll
        for (int k0 = 0; k0 < 32; k0 += 8) {
            uint32_t af[2][4], bf[4][2];
            #pragma unroll
            for (int mt = 0; mt < 2; mt++) {
                const int r0 = wm + mt * 16 + gq;
                af[mt][0] = __float_as_uint(As[s][r0][k0 + tq]);
                af[mt][1] = __float_as_uint(As[s][r0 + 8][k0 + tq]);
                af[mt][2] = __float_as_uint(As[s][r0][k0 + tq + 4]);
                af[mt][3] = __float_as_uint(As[s][r0 + 8][k0 + tq + 4]);
            }
            #pragma unroll
            for (int nt = 0; nt < 4; nt++) {
                bf[nt][0] = __float_as_uint(Bs[s][k0 + tq][wn + nt * 8 + gq]);
                bf[nt][1] = __float_as_uint(Bs[s][k0 + tq + 4][wn + nt * 8 + gq]);
            }
            #pragma unroll
            for (int mt = 0; mt < 2; mt++)
                #pragma unroll
                for (int nt = 0; nt < 4; nt++)
                    mma_tf32(c[mt][nt], af[mt], bf[nt]);
        }
        __syncthreads();
    }

    #pragma unroll
    for (int mt = 0; mt < 2; mt++)
        #pragma unroll
        for (int half = 0; half < 2; half++) {
            const int row = m0 + wm + mt * 16 + gq + half * 8;
            #pragma unroll
            for (int nt = 0; nt < 4; nt++) {
                const int col = n0 + wn + nt * 8 + 2 * tq;
                float2 r;
                r.x = c[mt][nt][half*2 + 0];
                r.y = c[mt][nt][half*2 + 1];
                *reinterpret_cast<float2*>(g_ctx + (size_t)(b*NC + row)*ND + col) = r;
            }
        }
}

// ------------- LayerNorm combine: v = P0 + P1 + bias + Res, then LN ---------
__global__ __launch_bounds__(128)
void ln_comb_kernel(const float* __restrict__ P,
                    const float* __restrict__ Res,
                    const float* __restrict__ bias,
                    const float* __restrict__ g, const float* __restrict__ be,
                    float* __restrict__ out) {
    const int row = blockIdx.x;
    const int tid = threadIdx.x;   // 128
    __shared__ float red_s[128];
    __shared__ float red_q[128];

    const size_t idx = (size_t)row*(ND/4) + tid;
    float4 p0 = reinterpret_cast<const float4*>(P)[idx];
    float4 p1 = reinterpret_cast<const float4*>(P + (size_t)ROWS*ND)[idx];
    float4 rs = reinterpret_cast<const float4*>(Res)[idx];
    float4 bb = reinterpret_cast<const float4*>(bias)[tid];
    float4 v;
    v.x = p0.x + p1.x + bb.x + rs.x;
    v.y = p0.y + p1.y + bb.y + rs.y;
    v.z = p0.z + p1.z + bb.z + rs.z;
    v.w = p0.w + p1.w + bb.w + rs.w;

    float s  = v.x + v.y + v.z + v.w;
    float sq = v.x*v.x + v.y*v.y + v.z*v.z + v.w*v.w;
    red_s[tid] = s; red_q[tid] = sq;
    __syncthreads();
    #pragma unroll
    for (int st = 64; st > 0; st >>= 1) {
        if (tid < st) { red_s[tid] += red_s[tid+st]; red_q[tid] += red_q[tid+st]; }
        __syncthreads();
    }
    const float mean = red_s[0] * (1.0f/ND);
    const float var  = red_q[0] * (1.0f/ND) - mean*mean;
    const float inv  = rsqrtf(var + 1e-5f);

    float4 g4 = reinterpret_cast<const float4*>(g)[tid];
    float4 b4 = reinterpret_cast<const float4*>(be)[tid];
    float4 r;
    r.x = (v.x - mean)*inv*g4.x + b4.x;
    r.y = (v.y - mean)*inv*g4.y + b4.y;
    r.z = (v.z - mean)*inv*g4.z + b4.z;
    r.w = (v.w - mean)*inv*g4.w + b4.w;
    reinterpret_cast<float4*>(out)[idx] = r;
}

// ---------------- launch ----------------------------------------------------
extern "C" void kernel_launch(void* const* d_in, const int* in_sizes, int n_in,
                              void* d_out, int out_size) {
    const float* x    = (const float*)d_in[0];
    const float* mask = (const float*)d_in[1];
    const float* Wqkv = (const float*)d_in[2];
    const float* bqkv = (const float*)d_in[3];
    const float* Wo   = (const float*)d_in[4];
    const float* bo   = (const float*)d_in[5];
    const float* W1   = (const float*)d_in[6];
    const float* b1   = (const float*)d_in[7];
    const float* W2   = (const float*)d_in[8];
    const float* b2   = (const float*)d_in[9];
    const float* g1   = (const float*)d_in[10];
    const float* be1  = (const float*)d_in[11];
    const float* g2   = (const float*)d_in[12];
    const float* be2  = (const float*)d_in[13];
    float* out = (float*)d_out;

    float *E0, *QKV, *ctx, *P, *E1, *H;
    float *Wqkv_tf, *Wo_tf, *W1_tf, *W2_tf;
    cudaGetSymbolAddress((void**)&E0,   g_E0);
    cudaGetSymbolAddress((void**)&QKV,  g_QKV);
    cudaGetSymbolAddress((void**)&ctx,  g_ctx);
    cudaGetSymbolAddress((void**)&P,    g_P);
    cudaGetSymbolAddress((void**)&E1,   g_E1);
    cudaGetSymbolAddress((void**)&H,    g_H);
    cudaGetSymbolAddress((void**)&Wqkv_tf, g_Wqkv);
    cudaGetSymbolAddress((void**)&Wo_tf,   g_Wo);
    cudaGetSymbolAddress((void**)&W1_tf,   g_W1);
    cudaGetSymbolAddress((void**)&W2_tf,   g_W2);

    // Side stream: ONLY the tiny weight-conversion overlapped under the
    // memory-bound pool. Created per call; graph replays are free.
    cudaStream_t s1;
    cudaStreamCreateWithFlags(&s1, cudaStreamNonBlocking);
    cudaEvent_t evFork, evCvt;
    cudaEventCreateWithFlags(&evFork, cudaEventDisableTiming);
    cudaEventCreateWithFlags(&evCvt,  cudaEventDisableTiming);

    cudaEventRecord(evFork, 0);
    cudaStreamWaitEvent(s1, evFork, 0);
    cvt_all_kernel<<<(NW_QKV+NW_O+NW_1+NW_2)/256, 256, 0, s1>>>(Wqkv, Wo, W1, W2);
    cudaEventRecord(evCvt, s1);

    // s0: masked mean pool (HBM-bound)
    pool_kernel<<<ROWS, 128>>>(x, mask);
    cudaStreamWaitEvent(0, evCvt, 0);

    // QKV = E0 @ Wqkv + bqkv     (2048 x 1536 x 512), A = raw fp32
    gemm_tc<EPI_BIAS><<<dim3(3*ND/128, ROWS/64), 256>>>(E0, Wqkv_tf, bqkv, QKV, ROWS, 3*ND, ND);

    // attention partial dots (4 split-K quarters)
    attn_scores_tc<<<dim3(2, 2, NB*4), 128>>>(mask);
    // modulate + softmax -> A (rna-rounded)
    attn_softmax<<<dim3(NC/8, NB), 128>>>(mask);
    // ctx = A @ V on tensor cores
    attn_av_tc<<<dim3(ND/64, NC/64, NB), 128>>>(mask);

    // P = ctx @ Wo (split-K=2 partials)   (2048 x 512 x 512)
    gemm_tc_sk<<<dim3(ND/128, ROWS/64, 2), 256>>>(ctx, Wo_tf, P, ROWS, ND, ND);

    // E1 = LN(P0+P1+bo+E0)
    ln_comb_kernel<<<ROWS, 128>>>(P, E0, bo, g1, be1, E1);

    // H = gelu(E1 @ W1 + b1)     (2048 x 1024 x 512)
    gemm_tc<EPI_GELU><<<dim3(2*ND/128, ROWS/64), 256>>>(E1, W1_tf, b1, H, ROWS, 2*ND, ND);

    // P = H @ W2 (split-K=2 partials)     (2048 x 512 x 1024)
    gemm_tc_sk<<<dim3(ND/128, ROWS/64, 2), 256>>>(H, W2_tf, P, ROWS, ND, 2*ND);

    // out = LN(P0+P1+b2+E1)
    ln_comb_kernel<<<ROWS, 128>>>(P, E1, b2, g2, be2, out);

    cudaEventDestroy(evFork);
    cudaEventDestroy(evCvt);
    cudaStreamDestroy(s1);
}